// round 4
// baseline (speedup 1.0000x reference)
#include <cuda_runtime.h>
#include <cooperative_groups.h>
#include <cstdint>

namespace cg = cooperative_groups;

#define NB    4
#define NPTS  16384
#define NC    64
#define NSMP  1024      // S (npoint)
#define NNEI  32        // nsample
#define D0    67        // 3 + C
#define D1    64
#define D2    64
#define D3    128

#define FCTAS 8                 // cluster size (CTAs per batch)
#define FTHR  256               // threads per FPS CTA
#define PPC   (NPTS / FCTAS)    // 2048 points per CTA
#define PPT   (PPC / FTHR)      // 8 points per thread

// scratch: ball query neighbor indices
__device__ int g_ball_idx[NB * NSMP * NNEI];

__device__ __forceinline__ unsigned smem_u32(const void* p) {
    return (unsigned)__cvta_generic_to_shared(p);
}
__device__ __forceinline__ unsigned mapa_u32(unsigned laddr, unsigned rank) {
    unsigned r;
    asm("mapa.shared::cluster.u32 %0, %1, %2;" : "=r"(r) : "r"(laddr), "r"(rank));
    return r;
}
__device__ __forceinline__ void mbar_init(unsigned addr, unsigned cnt) {
    asm volatile("mbarrier.init.shared.b64 [%0], %1;" :: "r"(addr), "r"(cnt) : "memory");
}
__device__ __forceinline__ void mbar_arrive_rel_cluster(unsigned raddr) {
    asm volatile("mbarrier.arrive.release.cluster.shared::cluster.b64 _, [%0];"
                 :: "r"(raddr) : "memory");
}
__device__ __forceinline__ void mbar_wait_acq_cluster(unsigned addr, unsigned parity) {
    asm volatile(
        "{\n\t"
        ".reg .pred P;\n"
        "WL_%=:\n\t"
        "mbarrier.try_wait.parity.acquire.cluster.shared::cta.b64 P, [%0], %1, 0x989680;\n\t"
        "@P bra WD_%=;\n\t"
        "bra WL_%=;\n"
        "WD_%=:\n\t"
        "}"
        :: "r"(addr), "r"(parity) : "memory");
}
__device__ __forceinline__ void st_cluster_f4(unsigned raddr, float x, float y, float z, float w) {
    asm volatile("st.shared::cluster.v4.f32 [%0], {%1,%2,%3,%4};"
                 :: "r"(raddr), "f"(x), "f"(y), "f"(z), "f"(w) : "memory");
}
__device__ __forceinline__ void st_cluster_u32(unsigned raddr, unsigned v) {
    asm volatile("st.shared::cluster.u32 [%0], %1;" :: "r"(raddr), "r"(v) : "memory");
}

// ---------------------------------------------------------------------------
// FPS: one 8-CTA cluster per batch, points register-resident.
// Packed u64 keys (dist_bits<<32 | ~gidx) -> single-value max reductions.
// Cross-CTA winner exchange via DSMEM record stores + mbarrier (release/acquire),
// double-buffered by step parity. One __syncthreads per step.
// ---------------------------------------------------------------------------
__global__ __launch_bounds__(FTHR, 1) __cluster_dims__(FCTAS, 1, 1)
void fps_cluster_kernel(const float* __restrict__ xyz, float* __restrict__ out_xyz) {
    __shared__ float sx[PPC], sy[PPC], sz[PPC];
    __shared__ float4 s_rec[2][FCTAS];                 // (x, y, z, dist)
    __shared__ unsigned s_lk[2][FCTAS];                // low key = ~gidx
    __shared__ unsigned long long s_wkey[FTHR / 32];   // per-warp winners
    __shared__ alignas(8) unsigned long long s_bar;

    cg::cluster_group cluster = cg::this_cluster();
    const int crank = cluster.block_rank();
    const int b     = blockIdx.x / FCTAS;
    const int tid   = threadIdx.x;
    const int lane  = tid & 31;
    const int wid   = tid >> 5;

    const float* base = xyz + (size_t)b * NPTS * 3;
    const int g0 = crank * PPC;

    // load this CTA's slice into smem SoA
    for (int k = tid; k < PPC * 3; k += FTHR) {
        float v = base[(size_t)g0 * 3 + k];
        int p = k / 3, c = k - 3 * p;
        if (c == 0)      sx[p] = v;
        else if (c == 1) sy[p] = v;
        else             sz[p] = v;
    }
    if (tid == 0) mbar_init(smem_u32(&s_bar), FCTAS);
    cluster.sync();   // barriers initialized + smem loaded, cluster-wide

    // register-resident points + distances
    float px[PPT], py[PPT], pz[PPT], dist[PPT];
#pragma unroll
    for (int j = 0; j < PPT; j++) {
        int i = tid + j * FTHR;
        px[j] = sx[i]; py[j] = sy[i]; pz[j] = sz[i];
        dist[j] = 3.4e38f;
    }

    // precompute remote addresses (warp 0, lane r -> peer rank r)
    unsigned a_rec[2], a_lk[2], a_bar = 0;
    if (wid == 0 && lane < FCTAS) {
        a_rec[0] = mapa_u32(smem_u32(&s_rec[0][crank]), lane);
        a_rec[1] = mapa_u32(smem_u32(&s_rec[1][crank]), lane);
        a_lk[0]  = mapa_u32(smem_u32(&s_lk[0][crank]),  lane);
        a_lk[1]  = mapa_u32(smem_u32(&s_lk[1][crank]),  lane);
        a_bar    = mapa_u32(smem_u32(&s_bar), lane);
    }
    const unsigned l_bar = smem_u32(&s_bar);

    // current centroid = point 0 of the batch
    float cx = base[0], cy = base[1], cz = base[2];

    float* oxy = out_xyz + (size_t)b * NSMP * 3;

    for (int s = 0; s < NSMP; s++) {
        if (crank == 0 && tid == 0) {
            oxy[s * 3 + 0] = cx; oxy[s * 3 + 1] = cy; oxy[s * 3 + 2] = cz;
        }

        // update + thread argmax as packed key (tie -> smaller global idx)
        unsigned long long bk = 0ull;
#pragma unroll
        for (int j = 0; j < PPT; j++) {
            float dx = px[j] - cx, dy = py[j] - cy, dz = pz[j] - cz;
            float d  = dx * dx + dy * dy + dz * dz;
            float nd = fminf(dist[j], d);
            dist[j] = nd;
            unsigned lk = 0xffffffffu - (unsigned)(g0 + tid + j * FTHR);
            unsigned long long key =
                ((unsigned long long)__float_as_uint(nd) << 32) | lk;
            if (key > bk) bk = key;
        }
        // warp max
#pragma unroll
        for (int off = 16; off; off >>= 1) {
            unsigned long long ok = __shfl_down_sync(0xffffffffu, bk, off);
            if (ok > bk) bk = ok;
        }
        if (lane == 0) s_wkey[wid] = bk;
        __syncthreads();

        const int par = s & 1;
        if (wid == 0) {
            unsigned long long k = (lane < FTHR / 32) ? s_wkey[lane] : 0ull;
            // butterfly over 8 (stays within each 8-lane octet)
#pragma unroll
            for (int off = 1; off < 8; off <<= 1) {
                unsigned long long ok = __shfl_xor_sync(0xffffffffu, k, off);
                if (ok > k) k = ok;
            }
            if (lane < FCTAS) {
                unsigned gidx = 0xffffffffu - (unsigned)k;
                int li = (int)gidx - g0;                       // CTA-local winner
                float wx = sx[li], wy = sy[li], wz = sz[li];   // broadcast LDS
                float wv = __uint_as_float((unsigned)(k >> 32));
                st_cluster_f4(a_rec[par], wx, wy, wz, wv);
                st_cluster_u32(a_lk[par], (unsigned)k);
                mbar_arrive_rel_cluster(a_bar);
            }
        }

        // everyone waits for all 8 records, then reduces redundantly
        mbar_wait_acq_cluster(l_bar, (unsigned)par);

        {
            int r = lane & 7;
            float4 rec = s_rec[par][r];
            unsigned lk2 = s_lk[par][r];
            unsigned long long ck =
                ((unsigned long long)__float_as_uint(rec.w) << 32) | lk2;
            unsigned long long km = ck;
#pragma unroll
            for (int off = 1; off < 8; off <<= 1) {
                unsigned long long ok = __shfl_xor_sync(0xffffffffu, km, off);
                if (ok > km) km = ok;
            }
            unsigned win = __ballot_sync(0xffffffffu, ck == km);
            int wl = __ffs(win) - 1;          // 0..7
            cx = __shfl_sync(0xffffffffu, rec.x, wl);
            cy = __shfl_sync(0xffffffffu, rec.y, wl);
            cz = __shfl_sync(0xffffffffu, rec.z, wl);
        }
    }
}

// ---------------------------------------------------------------------------
// Ball query: one warp per centroid. Collect first NNEI indices (scan order)
// with d2 <= r^2; pad remaining slots with the first hit. Early exit.
// ---------------------------------------------------------------------------
__global__ void ball_kernel(const float* __restrict__ xyz,
                            const float* __restrict__ new_xyz) {
    const int gw   = (blockIdx.x * blockDim.x + threadIdx.x) >> 5;
    const int lane = threadIdx.x & 31;
    if (gw >= NB * NSMP) return;
    const int b = gw >> 10;
    const float* base = xyz + (size_t)b * NPTS * 3;
    const float cx = new_xyz[gw * 3 + 0];
    const float cy = new_xyz[gw * 3 + 1];
    const float cz = new_xyz[gw * 3 + 2];
    const float r2 = 0.2f * 0.2f;
    int* out = g_ball_idx + gw * NNEI;

    int cnt = 0, first = 0;
    for (int j0 = 0; j0 < NPTS; j0 += 32) {
        const int j = j0 + lane;
        float dx = base[3 * j]     - cx;
        float dy = base[3 * j + 1] - cy;
        float dz = base[3 * j + 2] - cz;
        float d2 = dx * dx + dy * dy + dz * dz;
        bool hit = (d2 <= r2);
        unsigned m = __ballot_sync(0xffffffffu, hit);
        if (m) {
            if (cnt == 0) first = j0 + (__ffs(m) - 1);
            int pos = cnt + __popc(m & ((1u << lane) - 1u));
            if (hit && pos < NNEI) out[pos] = j;
            cnt += __popc(m);
            if (cnt >= NNEI) break;
        }
    }
    if (cnt < NNEI) {
        for (int p = cnt + lane; p < NNEI; p += 32) out[p] = first;
    }
}

// ---------------------------------------------------------------------------
// Fused grouping + 3-layer MLP + maxpool. One block (256 thr) per centroid.
// Register-tiled: each thread owns 2 neighbors x 4 (or 8) channels;
// weights read as float4 from smem.
// ---------------------------------------------------------------------------
__global__ __launch_bounds__(256, 3)
void group_mlp_kernel(const float* __restrict__ xyz,
                      const float* __restrict__ feat,
                      const float* __restrict__ W0, const float* __restrict__ b0,
                      const float* __restrict__ W1, const float* __restrict__ b1,
                      const float* __restrict__ W2, const float* __restrict__ b2,
                      const float* __restrict__ new_xyz,
                      float* __restrict__ out_feat) {
    extern __shared__ float sm[];
    float* W    = sm;                    // up to 8192 floats
    float* bias = W + 8192;              // 128
    float* hA   = bias + 128;            // 32*67 = 2144
    float* hB   = hA + 2144;             // 32*128 = 4096
    float* hC   = hB + 4096;             // 32*64  = 2048
    __shared__ int s_ni[NNEI];

    const int cid = blockIdx.x;          // 0 .. NB*NSMP-1
    const int b   = cid >> 10;
    const int tid = threadIdx.x;

    if (tid < NNEI) s_ni[tid] = g_ball_idx[cid * NNEI + tid];
    for (int i = tid; i < D0 * D1; i += 256) W[i] = W0[i];
    if (tid < D1) bias[tid] = b0[tid];
    __syncthreads();

    const float* xb = xyz  + (size_t)b * NPTS * 3;
    const float* fb = feat + (size_t)b * NPTS * NC;

    // build h0 = [g_xyz - centroid, g_feat]
    for (int e = tid; e < NNEI * 3; e += 256) {
        int ns = e / 3, k = e - 3 * ns;
        hA[ns * D0 + k] = xb[(size_t)s_ni[ns] * 3 + k] - new_xyz[cid * 3 + k];
    }
    for (int e = tid; e < NNEI * NC; e += 256) {
        int ns = e >> 6, c = e & 63;
        hA[ns * D0 + 3 + c] = fb[(size_t)s_ni[ns] * NC + c];
    }
    __syncthreads();

    const int chq = tid & 15;            // channel quad index (16 quads)
    const int ns0 = (tid >> 4) * 2;      // neighbor pair

    // ---- layer 1: hA(67) -> hB(64), 2 ns x 4 ch per thread ----
    {
        float4 bs = *(float4*)&bias[chq * 4];
        float a00 = bs.x, a01 = bs.y, a02 = bs.z, a03 = bs.w;
        float a10 = bs.x, a11 = bs.y, a12 = bs.z, a13 = bs.w;
        const float* h0 = hA + ns0 * D0;
        const float* h1 = hA + (ns0 + 1) * D0;
#pragma unroll 4
        for (int d = 0; d < D0; d++) {
            float v0 = h0[d], v1 = h1[d];
            float4 w = *(float4*)&W[d * D1 + chq * 4];
            a00 = fmaf(v0, w.x, a00); a01 = fmaf(v0, w.y, a01);
            a02 = fmaf(v0, w.z, a02); a03 = fmaf(v0, w.w, a03);
            a10 = fmaf(v1, w.x, a10); a11 = fmaf(v1, w.y, a11);
            a12 = fmaf(v1, w.z, a12); a13 = fmaf(v1, w.w, a13);
        }
        *(float4*)&hB[ns0 * D1 + chq * 4] =
            make_float4(fmaxf(a00, 0.f), fmaxf(a01, 0.f), fmaxf(a02, 0.f), fmaxf(a03, 0.f));
        *(float4*)&hB[(ns0 + 1) * D1 + chq * 4] =
            make_float4(fmaxf(a10, 0.f), fmaxf(a11, 0.f), fmaxf(a12, 0.f), fmaxf(a13, 0.f));
    }
    __syncthreads();

    for (int i = tid; i < D1 * D2; i += 256) W[i] = W1[i];
    if (tid < D2) bias[tid] = b1[tid];
    __syncthreads();

    // ---- layer 2: hB(64) -> hC(64) ----
    {
        float4 bs = *(float4*)&bias[chq * 4];
        float a00 = bs.x, a01 = bs.y, a02 = bs.z, a03 = bs.w;
        float a10 = bs.x, a11 = bs.y, a12 = bs.z, a13 = bs.w;
        const float* h0 = hB + ns0 * D1;
        const float* h1 = hB + (ns0 + 1) * D1;
#pragma unroll 4
        for (int d = 0; d < D1; d++) {
            float v0 = h0[d], v1 = h1[d];
            float4 w = *(float4*)&W[d * D2 + chq * 4];
            a00 = fmaf(v0, w.x, a00); a01 = fmaf(v0, w.y, a01);
            a02 = fmaf(v0, w.z, a02); a03 = fmaf(v0, w.w, a03);
            a10 = fmaf(v1, w.x, a10); a11 = fmaf(v1, w.y, a11);
            a12 = fmaf(v1, w.z, a12); a13 = fmaf(v1, w.w, a13);
        }
        *(float4*)&hC[ns0 * D2 + chq * 4] =
            make_float4(fmaxf(a00, 0.f), fmaxf(a01, 0.f), fmaxf(a02, 0.f), fmaxf(a03, 0.f));
        *(float4*)&hC[(ns0 + 1) * D2 + chq * 4] =
            make_float4(fmaxf(a10, 0.f), fmaxf(a11, 0.f), fmaxf(a12, 0.f), fmaxf(a13, 0.f));
    }
    __syncthreads();

    for (int i = tid; i < D2 * D3; i += 256) W[i] = W2[i];
    if (tid < D3) bias[tid] = b2[tid];
    __syncthreads();

    // ---- layer 3: hC(64) -> hB(128), 2 ns x 8 ch per thread ----
    {
        const int ch8 = chq * 8;
        float4 bs0 = *(float4*)&bias[ch8];
        float4 bs1 = *(float4*)&bias[ch8 + 4];
        float a0[8] = {bs0.x, bs0.y, bs0.z, bs0.w, bs1.x, bs1.y, bs1.z, bs1.w};
        float a1[8] = {bs0.x, bs0.y, bs0.z, bs0.w, bs1.x, bs1.y, bs1.z, bs1.w};
        const float* h0 = hC + ns0 * D2;
        const float* h1 = hC + (ns0 + 1) * D2;
#pragma unroll 4
        for (int d = 0; d < D2; d++) {
            float v0 = h0[d], v1 = h1[d];
            float4 w0 = *(float4*)&W[d * D3 + ch8];
            float4 w1 = *(float4*)&W[d * D3 + ch8 + 4];
            a0[0] = fmaf(v0, w0.x, a0[0]); a0[1] = fmaf(v0, w0.y, a0[1]);
            a0[2] = fmaf(v0, w0.z, a0[2]); a0[3] = fmaf(v0, w0.w, a0[3]);
            a0[4] = fmaf(v0, w1.x, a0[4]); a0[5] = fmaf(v0, w1.y, a0[5]);
            a0[6] = fmaf(v0, w1.z, a0[6]); a0[7] = fmaf(v0, w1.w, a0[7]);
            a1[0] = fmaf(v1, w0.x, a1[0]); a1[1] = fmaf(v1, w0.y, a1[1]);
            a1[2] = fmaf(v1, w0.z, a1[2]); a1[3] = fmaf(v1, w0.w, a1[3]);
            a1[4] = fmaf(v1, w1.x, a1[4]); a1[5] = fmaf(v1, w1.y, a1[5]);
            a1[6] = fmaf(v1, w1.z, a1[6]); a1[7] = fmaf(v1, w1.w, a1[7]);
        }
        *(float4*)&hB[ns0 * D3 + ch8] =
            make_float4(fmaxf(a0[0], 0.f), fmaxf(a0[1], 0.f), fmaxf(a0[2], 0.f), fmaxf(a0[3], 0.f));
        *(float4*)&hB[ns0 * D3 + ch8 + 4] =
            make_float4(fmaxf(a0[4], 0.f), fmaxf(a0[5], 0.f), fmaxf(a0[6], 0.f), fmaxf(a0[7], 0.f));
        *(float4*)&hB[(ns0 + 1) * D3 + ch8] =
            make_float4(fmaxf(a1[0], 0.f), fmaxf(a1[1], 0.f), fmaxf(a1[2], 0.f), fmaxf(a1[3], 0.f));
        *(float4*)&hB[(ns0 + 1) * D3 + ch8 + 4] =
            make_float4(fmaxf(a1[4], 0.f), fmaxf(a1[5], 0.f), fmaxf(a1[6], 0.f), fmaxf(a1[7], 0.f));
    }
    __syncthreads();

    // maxpool over neighbors
    for (int dj = tid; dj < D3; dj += 256) {
        float m = hB[dj];
#pragma unroll 4
        for (int ns = 1; ns < NNEI; ns++) m = fmaxf(m, hB[ns * D3 + dj]);
        out_feat[(size_t)cid * D3 + dj] = m;
    }
}

// ---------------------------------------------------------------------------
extern "C" void kernel_launch(void* const* d_in, const int* in_sizes, int n_in,
                              void* d_out, int out_size) {
    const float* xyz  = (const float*)d_in[0];
    const float* feat = (const float*)d_in[1];
    const float* W0   = (const float*)d_in[2];
    const float* b0   = (const float*)d_in[3];
    const float* W1   = (const float*)d_in[4];
    const float* b1   = (const float*)d_in[5];
    const float* W2   = (const float*)d_in[6];
    const float* b2   = (const float*)d_in[7];

    float* out      = (float*)d_out;
    float* new_xyz  = out;                       // B*S*3
    float* out_feat = out + NB * NSMP * 3;       // B*S*128

    const int mlp_smem = (8192 + 128 + 2144 + 4096 + 2048) * 4;  // 66432
    cudaFuncSetAttribute(group_mlp_kernel, cudaFuncAttributeMaxDynamicSharedMemorySize, mlp_smem);

    fps_cluster_kernel<<<NB * FCTAS, FTHR>>>(xyz, new_xyz);

    const int bq_threads = 256;
    const int bq_blocks  = (NB * NSMP * 32 + bq_threads - 1) / bq_threads;
    ball_kernel<<<bq_blocks, bq_threads>>>(xyz, new_xyz);

    group_mlp_kernel<<<NB * NSMP, 256, mlp_smem>>>(
        xyz, feat, W0, b0, W1, b1, W2, b2, new_xyz, out_feat);
}

// round 5
// speedup vs baseline: 1.1403x; 1.1403x over previous
#include <cuda_runtime.h>
#include <cooperative_groups.h>
#include <cstdint>

namespace cg = cooperative_groups;

#define NB    4
#define NPTS  16384
#define NC    64
#define NSMP  1024      // S (npoint)
#define NNEI  32        // nsample
#define D0    67        // 3 + C
#define D1    64
#define D2    64
#define D3    128

#define FCTAS 8                 // cluster size (CTAs per batch)
#define FTHR  256               // threads per FPS CTA
#define PPC   (NPTS / FCTAS)    // 2048 points per CTA
#define PPT   (PPC / FTHR)      // 8 points per thread

// scratch: ball query neighbor indices
__device__ int g_ball_idx[NB * NSMP * NNEI];

__device__ __forceinline__ unsigned smem_u32(const void* p) {
    return (unsigned)__cvta_generic_to_shared(p);
}
__device__ __forceinline__ unsigned mapa_u32(unsigned laddr, unsigned rank) {
    unsigned r;
    asm("mapa.shared::cluster.u32 %0, %1, %2;" : "=r"(r) : "r"(laddr), "r"(rank));
    return r;
}
__device__ __forceinline__ void st_cluster_f4(unsigned raddr, float x, float y, float z, float w) {
    asm volatile("st.shared::cluster.v4.f32 [%0], {%1,%2,%3,%4};"
                 :: "r"(raddr), "f"(x), "f"(y), "f"(z), "f"(w) : "memory");
}
__device__ __forceinline__ void st_cluster_u32(unsigned raddr, unsigned v) {
    asm volatile("st.shared::cluster.u32 [%0], %1;" :: "r"(raddr), "r"(v) : "memory");
}
__device__ __forceinline__ unsigned redux_max_u32(unsigned v) {
    unsigned r;
    asm("redux.sync.max.u32 %0, %1, 0xffffffff;" : "=r"(r) : "r"(v));
    return r;
}
__device__ __forceinline__ unsigned redux_min_u32(unsigned v) {
    unsigned r;
    asm("redux.sync.min.u32 %0, %1, 0xffffffff;" : "=r"(r) : "r"(v));
    return r;
}
__device__ __forceinline__ void cluster_arrive() {
    asm volatile("barrier.cluster.arrive.aligned;" ::: "memory");
}
__device__ __forceinline__ void cluster_wait() {
    asm volatile("barrier.cluster.wait.aligned;" ::: "memory");
}

// ---------------------------------------------------------------------------
// FPS: one 8-CTA cluster per batch, points register-resident.
// Warp argmax via redux.sync (max dist-bits, then min gidx among ties).
// CTA stage + final 8-record stage are serial register reductions (no shfl).
// Cross-CTA exchange: DSMEM record stores + raw barrier.cluster arrive/wait,
// record slots double-buffered by step parity.
// ---------------------------------------------------------------------------
__global__ __launch_bounds__(FTHR, 1) __cluster_dims__(FCTAS, 1, 1)
void fps_cluster_kernel(const float* __restrict__ xyz, float* __restrict__ out_xyz) {
    __shared__ float sx[PPC], sy[PPC], sz[PPC];
    __shared__ float4 s_rec[2][FCTAS];                 // (x, y, z, dist)
    __shared__ unsigned s_lk[2][FCTAS];                // low key = ~gidx
    __shared__ unsigned long long s_wkey[FTHR / 32];   // per-warp winner keys

    cg::cluster_group cluster = cg::this_cluster();
    const int crank = cluster.block_rank();
    const int b     = blockIdx.x / FCTAS;
    const int tid   = threadIdx.x;
    const int lane  = tid & 31;
    const int wid   = tid >> 5;

    const float* base = xyz + (size_t)b * NPTS * 3;
    const int g0 = crank * PPC;

    // load this CTA's slice into smem SoA
    for (int k = tid; k < PPC * 3; k += FTHR) {
        float v = base[(size_t)g0 * 3 + k];
        int p = k / 3, c = k - 3 * p;
        if (c == 0)      sx[p] = v;
        else if (c == 1) sy[p] = v;
        else             sz[p] = v;
    }
    cluster.sync();   // smem slices visible cluster-wide

    // register-resident points + distances
    float px[PPT], py[PPT], pz[PPT], dist[PPT];
#pragma unroll
    for (int j = 0; j < PPT; j++) {
        int i = tid + j * FTHR;
        px[j] = sx[i]; py[j] = sy[i]; pz[j] = sz[i];
        dist[j] = 3.4e38f;
    }

    // remote record addresses (warp 0, lane r -> peer rank r)
    unsigned a_rec[2], a_lk[2];
    if (wid == 0 && lane < FCTAS) {
        a_rec[0] = mapa_u32(smem_u32(&s_rec[0][crank]), lane);
        a_rec[1] = mapa_u32(smem_u32(&s_rec[1][crank]), lane);
        a_lk[0]  = mapa_u32(smem_u32(&s_lk[0][crank]),  lane);
        a_lk[1]  = mapa_u32(smem_u32(&s_lk[1][crank]),  lane);
    }

    // current centroid = point 0 of the batch
    float cx = base[0], cy = base[1], cz = base[2];

    float* oxy = out_xyz + (size_t)b * NSMP * 3;

    for (int s = 0; s < NSMP; s++) {
        if (crank == 0 && tid == 0) {
            oxy[s * 3 + 0] = cx; oxy[s * 3 + 1] = cy; oxy[s * 3 + 2] = cz;
        }

        // update + thread argmax (ascending local idx -> first max kept)
        float bv = -1.0f; int bi = 0;
#pragma unroll
        for (int j = 0; j < PPT; j++) {
            float dx = px[j] - cx, dy = py[j] - cy, dz = pz[j] - cz;
            float d  = dx * dx + dy * dy + dz * dz;
            float nd = fminf(dist[j], d);
            dist[j] = nd;
            if (nd > bv) { bv = nd; bi = tid + j * FTHR; }
        }

        // warp argmax via redux: max dist-bits, then min global idx among ties
        unsigned db = __float_as_uint(bv);           // bv >= 0 -> order-preserving
        unsigned mx = redux_max_u32(db);
        unsigned gi = (unsigned)(g0 + bi);
        unsigned cand = (db == mx) ? gi : 0xffffffffu;
        unsigned mi = redux_min_u32(cand);
        if (lane == 0)
            s_wkey[wid] = ((unsigned long long)mx << 32) | (0xffffffffu - mi);
        __syncthreads();

        const int par = s & 1;
        if (wid == 0) {
            // serial max over the 8 warp keys (broadcast LDS, no shuffles)
            unsigned long long k = s_wkey[0];
#pragma unroll
            for (int w = 1; w < FTHR / 32; w++) {
                unsigned long long t = s_wkey[w];
                if (t > k) k = t;
            }
            if (lane < FCTAS) {
                unsigned g  = 0xffffffffu - (unsigned)k;
                int li = (int)g - g0;                        // CTA-local winner
                st_cluster_f4(a_rec[par], sx[li], sy[li], sz[li],
                              __uint_as_float((unsigned)(k >> 32)));
                st_cluster_u32(a_lk[par], (unsigned)k);
            }
        }
        cluster_arrive();
        cluster_wait();

        // all threads serially reduce the 8 records (deterministic winner)
        {
            unsigned long long km = 0ull;
            float X = 0.f, Y = 0.f, Z = 0.f;
#pragma unroll
            for (int r = 0; r < FCTAS; r++) {
                float4 rec = s_rec[par][r];
                unsigned lk = s_lk[par][r];
                unsigned long long ck =
                    ((unsigned long long)__float_as_uint(rec.w) << 32) | lk;
                if (ck > km) { km = ck; X = rec.x; Y = rec.y; Z = rec.z; }
            }
            cx = X; cy = Y; cz = Z;
        }
    }
}

// ---------------------------------------------------------------------------
// Ball query: one warp per centroid. Collect first NNEI indices (scan order)
// with d2 <= r^2; pad remaining slots with the first hit. Early exit.
// ---------------------------------------------------------------------------
__global__ void ball_kernel(const float* __restrict__ xyz,
                            const float* __restrict__ new_xyz) {
    const int gw   = (blockIdx.x * blockDim.x + threadIdx.x) >> 5;
    const int lane = threadIdx.x & 31;
    if (gw >= NB * NSMP) return;
    const int b = gw >> 10;
    const float* base = xyz + (size_t)b * NPTS * 3;
    const float cx = new_xyz[gw * 3 + 0];
    const float cy = new_xyz[gw * 3 + 1];
    const float cz = new_xyz[gw * 3 + 2];
    const float r2 = 0.2f * 0.2f;
    int* out = g_ball_idx + gw * NNEI;

    int cnt = 0, first = 0;
    for (int j0 = 0; j0 < NPTS; j0 += 32) {
        const int j = j0 + lane;
        float dx = base[3 * j]     - cx;
        float dy = base[3 * j + 1] - cy;
        float dz = base[3 * j + 2] - cz;
        float d2 = dx * dx + dy * dy + dz * dz;
        bool hit = (d2 <= r2);
        unsigned m = __ballot_sync(0xffffffffu, hit);
        if (m) {
            if (cnt == 0) first = j0 + (__ffs(m) - 1);
            int pos = cnt + __popc(m & ((1u << lane) - 1u));
            if (hit && pos < NNEI) out[pos] = j;
            cnt += __popc(m);
            if (cnt >= NNEI) break;
        }
    }
    if (cnt < NNEI) {
        for (int p = cnt + lane; p < NNEI; p += 32) out[p] = first;
    }
}

// ---------------------------------------------------------------------------
// Fused grouping + 3-layer MLP + maxpool. One block (256 thr) per centroid.
// Register-tiled: each thread owns 2 neighbors x 4 (or 8) channels;
// weights read as float4 from smem.
// ---------------------------------------------------------------------------
__global__ __launch_bounds__(256, 3)
void group_mlp_kernel(const float* __restrict__ xyz,
                      const float* __restrict__ feat,
                      const float* __restrict__ W0, const float* __restrict__ b0,
                      const float* __restrict__ W1, const float* __restrict__ b1,
                      const float* __restrict__ W2, const float* __restrict__ b2,
                      const float* __restrict__ new_xyz,
                      float* __restrict__ out_feat) {
    extern __shared__ float sm[];
    float* W    = sm;                    // up to 8192 floats
    float* bias = W + 8192;              // 128
    float* hA   = bias + 128;            // 32*67 = 2144
    float* hB   = hA + 2144;             // 32*128 = 4096
    float* hC   = hB + 4096;             // 32*64  = 2048
    __shared__ int s_ni[NNEI];

    const int cid = blockIdx.x;          // 0 .. NB*NSMP-1
    const int b   = cid >> 10;
    const int tid = threadIdx.x;

    if (tid < NNEI) s_ni[tid] = g_ball_idx[cid * NNEI + tid];
    for (int i = tid; i < D0 * D1; i += 256) W[i] = W0[i];
    if (tid < D1) bias[tid] = b0[tid];
    __syncthreads();

    const float* xb = xyz  + (size_t)b * NPTS * 3;
    const float* fb = feat + (size_t)b * NPTS * NC;

    // build h0 = [g_xyz - centroid, g_feat]
    for (int e = tid; e < NNEI * 3; e += 256) {
        int ns = e / 3, k = e - 3 * ns;
        hA[ns * D0 + k] = xb[(size_t)s_ni[ns] * 3 + k] - new_xyz[cid * 3 + k];
    }
    for (int e = tid; e < NNEI * NC; e += 256) {
        int ns = e >> 6, c = e & 63;
        hA[ns * D0 + 3 + c] = fb[(size_t)s_ni[ns] * NC + c];
    }
    __syncthreads();

    const int chq = tid & 15;            // channel quad index (16 quads)
    const int ns0 = (tid >> 4) * 2;      // neighbor pair

    // ---- layer 1: hA(67) -> hB(64), 2 ns x 4 ch per thread ----
    {
        float4 bs = *(float4*)&bias[chq * 4];
        float a00 = bs.x, a01 = bs.y, a02 = bs.z, a03 = bs.w;
        float a10 = bs.x, a11 = bs.y, a12 = bs.z, a13 = bs.w;
        const float* h0 = hA + ns0 * D0;
        const float* h1 = hA + (ns0 + 1) * D0;
#pragma unroll 4
        for (int d = 0; d < D0; d++) {
            float v0 = h0[d], v1 = h1[d];
            float4 w = *(float4*)&W[d * D1 + chq * 4];
            a00 = fmaf(v0, w.x, a00); a01 = fmaf(v0, w.y, a01);
            a02 = fmaf(v0, w.z, a02); a03 = fmaf(v0, w.w, a03);
            a10 = fmaf(v1, w.x, a10); a11 = fmaf(v1, w.y, a11);
            a12 = fmaf(v1, w.z, a12); a13 = fmaf(v1, w.w, a13);
        }
        *(float4*)&hB[ns0 * D1 + chq * 4] =
            make_float4(fmaxf(a00, 0.f), fmaxf(a01, 0.f), fmaxf(a02, 0.f), fmaxf(a03, 0.f));
        *(float4*)&hB[(ns0 + 1) * D1 + chq * 4] =
            make_float4(fmaxf(a10, 0.f), fmaxf(a11, 0.f), fmaxf(a12, 0.f), fmaxf(a13, 0.f));
    }
    __syncthreads();

    for (int i = tid; i < D1 * D2; i += 256) W[i] = W1[i];
    if (tid < D2) bias[tid] = b1[tid];
    __syncthreads();

    // ---- layer 2: hB(64) -> hC(64) ----
    {
        float4 bs = *(float4*)&bias[chq * 4];
        float a00 = bs.x, a01 = bs.y, a02 = bs.z, a03 = bs.w;
        float a10 = bs.x, a11 = bs.y, a12 = bs.z, a13 = bs.w;
        const float* h0 = hB + ns0 * D1;
        const float* h1 = hB + (ns0 + 1) * D1;
#pragma unroll 4
        for (int d = 0; d < D1; d++) {
            float v0 = h0[d], v1 = h1[d];
            float4 w = *(float4*)&W[d * D2 + chq * 4];
            a00 = fmaf(v0, w.x, a00); a01 = fmaf(v0, w.y, a01);
            a02 = fmaf(v0, w.z, a02); a03 = fmaf(v0, w.w, a03);
            a10 = fmaf(v1, w.x, a10); a11 = fmaf(v1, w.y, a11);
            a12 = fmaf(v1, w.z, a12); a13 = fmaf(v1, w.w, a13);
        }
        *(float4*)&hC[ns0 * D2 + chq * 4] =
            make_float4(fmaxf(a00, 0.f), fmaxf(a01, 0.f), fmaxf(a02, 0.f), fmaxf(a03, 0.f));
        *(float4*)&hC[(ns0 + 1) * D2 + chq * 4] =
            make_float4(fmaxf(a10, 0.f), fmaxf(a11, 0.f), fmaxf(a12, 0.f), fmaxf(a13, 0.f));
    }
    __syncthreads();

    for (int i = tid; i < D2 * D3; i += 256) W[i] = W2[i];
    if (tid < D3) bias[tid] = b2[tid];
    __syncthreads();

    // ---- layer 3: hC(64) -> hB(128), 2 ns x 8 ch per thread ----
    {
        const int ch8 = chq * 8;
        float4 bs0 = *(float4*)&bias[ch8];
        float4 bs1 = *(float4*)&bias[ch8 + 4];
        float a0[8] = {bs0.x, bs0.y, bs0.z, bs0.w, bs1.x, bs1.y, bs1.z, bs1.w};
        float a1[8] = {bs0.x, bs0.y, bs0.z, bs0.w, bs1.x, bs1.y, bs1.z, bs1.w};
        const float* h0 = hC + ns0 * D2;
        const float* h1 = hC + (ns0 + 1) * D2;
#pragma unroll 4
        for (int d = 0; d < D2; d++) {
            float v0 = h0[d], v1 = h1[d];
            float4 w0 = *(float4*)&W[d * D3 + ch8];
            float4 w1 = *(float4*)&W[d * D3 + ch8 + 4];
            a0[0] = fmaf(v0, w0.x, a0[0]); a0[1] = fmaf(v0, w0.y, a0[1]);
            a0[2] = fmaf(v0, w0.z, a0[2]); a0[3] = fmaf(v0, w0.w, a0[3]);
            a0[4] = fmaf(v0, w1.x, a0[4]); a0[5] = fmaf(v0, w1.y, a0[5]);
            a0[6] = fmaf(v0, w1.z, a0[6]); a0[7] = fmaf(v0, w1.w, a0[7]);
            a1[0] = fmaf(v1, w0.x, a1[0]); a1[1] = fmaf(v1, w0.y, a1[1]);
            a1[2] = fmaf(v1, w0.z, a1[2]); a1[3] = fmaf(v1, w0.w, a1[3]);
            a1[4] = fmaf(v1, w1.x, a1[4]); a1[5] = fmaf(v1, w1.y, a1[5]);
            a1[6] = fmaf(v1, w1.z, a1[6]); a1[7] = fmaf(v1, w1.w, a1[7]);
        }
        *(float4*)&hB[ns0 * D3 + ch8] =
            make_float4(fmaxf(a0[0], 0.f), fmaxf(a0[1], 0.f), fmaxf(a0[2], 0.f), fmaxf(a0[3], 0.f));
        *(float4*)&hB[ns0 * D3 + ch8 + 4] =
            make_float4(fmaxf(a0[4], 0.f), fmaxf(a0[5], 0.f), fmaxf(a0[6], 0.f), fmaxf(a0[7], 0.f));
        *(float4*)&hB[(ns0 + 1) * D3 + ch8] =
            make_float4(fmaxf(a1[0], 0.f), fmaxf(a1[1], 0.f), fmaxf(a1[2], 0.f), fmaxf(a1[3], 0.f));
        *(float4*)&hB[(ns0 + 1) * D3 + ch8 + 4] =
            make_float4(fmaxf(a1[4], 0.f), fmaxf(a1[5], 0.f), fmaxf(a1[6], 0.f), fmaxf(a1[7], 0.f));
    }
    __syncthreads();

    // maxpool over neighbors
    for (int dj = tid; dj < D3; dj += 256) {
        float m = hB[dj];
#pragma unroll 4
        for (int ns = 1; ns < NNEI; ns++) m = fmaxf(m, hB[ns * D3 + dj]);
        out_feat[(size_t)cid * D3 + dj] = m;
    }
}

// ---------------------------------------------------------------------------
extern "C" void kernel_launch(void* const* d_in, const int* in_sizes, int n_in,
                              void* d_out, int out_size) {
    const float* xyz  = (const float*)d_in[0];
    const float* feat = (const float*)d_in[1];
    const float* W0   = (const float*)d_in[2];
    const float* b0   = (const float*)d_in[3];
    const float* W1   = (const float*)d_in[4];
    const float* b1   = (const float*)d_in[5];
    const float* W2   = (const float*)d_in[6];
    const float* b2   = (const float*)d_in[7];

    float* out      = (float*)d_out;
    float* new_xyz  = out;                       // B*S*3
    float* out_feat = out + NB * NSMP * 3;       // B*S*128

    const int mlp_smem = (8192 + 128 + 2144 + 4096 + 2048) * 4;  // 66432
    cudaFuncSetAttribute(group_mlp_kernel, cudaFuncAttributeMaxDynamicSharedMemorySize, mlp_smem);

    fps_cluster_kernel<<<NB * FCTAS, FTHR>>>(xyz, new_xyz);

    const int bq_threads = 256;
    const int bq_blocks  = (NB * NSMP * 32 + bq_threads - 1) / bq_threads;
    ball_kernel<<<bq_blocks, bq_threads>>>(xyz, new_xyz);

    group_mlp_kernel<<<NB * NSMP, 256, mlp_smem>>>(
        xyz, feat, W0, b0, W1, b1, W2, b2, new_xyz, out_feat);
}